// round 6
// baseline (speedup 1.0000x reference)
#include <cuda_runtime.h>
#include <cstdint>

#define KQW      50
#define NCH      128          // key/value channels
#define NBINS    4096
#define CAND_CAP 32768
#define FCAP     2048         // filtered candidates in k_final
#define MAXN     1048576
#define NB_DIST  304          // 152 SMs * 2 blocks (smem-limited)

#define RT       32           // rows per tile
#define STAGES   4
#define TILE_F4  (RT * 32)    // 1024 float4 = 16KB per tile

// ---- scratch (device globals, zero at module load; kernels self-clean) ----
__device__ float    g_w[MAXN];          // per-row weights (4 MB)
__device__ float    g_bsum[NB_DIST];    // per-block partial sums of weights
__device__ unsigned g_hist[NBINS];      // coarse histogram (bits >> 19)
__device__ float    g_wsum;             // total weight sum
__device__ unsigned g_thresh_bin;       // boundary coarse bin b*
__device__ unsigned g_above;            // count strictly above b* (< 50)
__device__ unsigned g_done;             // k_dist completion counter
__device__ unsigned g_ncand;            // candidate counter
__device__ int      g_cand[CAND_CAP];   // candidate row indices
__device__ unsigned g_cwb[CAND_CAP];    // candidate weight bits

__device__ __forceinline__ unsigned coarse_bin(unsigned u) { return u >> 19; }
__device__ __forceinline__ unsigned sub_bin(unsigned u)    { return (u >> 7) & 0xFFFu; }

__device__ __forceinline__ void cp_async16(void* smem_dst, const void* gsrc) {
    unsigned s = (unsigned)__cvta_generic_to_shared(smem_dst);
    asm volatile("cp.async.cg.shared.global [%0], [%1], 16;" :: "r"(s), "l"(gsrc));
}
__device__ __forceinline__ void cp_commit() {
    asm volatile("cp.async.commit_group;" ::: "memory");
}
__device__ __forceinline__ void cp_wait3() {
    asm volatile("cp.async.wait_group 3;" ::: "memory");
}
__device__ __forceinline__ void cp_wait_all() {
    asm volatile("cp.async.wait_all;" ::: "memory");
}

// ------------------------------------------------------------------
// Parallel boundary-bin search over a 4096-bin histogram in smem.
// Smallest bin b* with suffix-count >= need. One thread writes out.
// ------------------------------------------------------------------
__device__ __forceinline__ void find_boundary(
    const unsigned* __restrict__ h, unsigned need,
    unsigned* csum, unsigned* suf,
    unsigned* out_bin, unsigned* out_above)
{
    const int tid = threadIdx.x;
    unsigned s = 0u;
    const int base = tid * (NBINS / 256);
    #pragma unroll
    for (int i = 0; i < NBINS / 256; i++) s += h[base + i];
    csum[tid] = s;
    suf[tid]  = s;
    __syncthreads();
    #pragma unroll
    for (int o = 1; o < 256; o <<= 1) {
        unsigned v = suf[tid];
        unsigned add = (tid + o < 256) ? suf[tid + o] : 0u;
        __syncthreads();
        suf[tid] = v + add;
        __syncthreads();
    }
    unsigned above_chunks = (tid + 1 < 256) ? suf[tid + 1] : 0u;
    if (above_chunks < need && suf[tid] >= need) {
        unsigned cum = above_chunks;
        int b = base + (NBINS / 256) - 1;
        for (;; b--) {
            if (b <= base) break;
            if (cum + h[b] >= need) break;
            cum += h[b];
        }
        *out_bin = (unsigned)b;
        *out_above = cum;
    }
}

// ------------------------------------------------------------------
// K1: 512MB stream via cp.async smem pipeline + fused threshold.
// Block: 256 threads. Tile = 32 rows (16KB), 4 stages in flight.
// Compute: warp w reduces rows [4w, 4w+4) of the tile from smem
// (LDS.128 conflict-free), grouped shuffle reduce -> 4 rows/warp.
// ------------------------------------------------------------------
__global__ void __launch_bounds__(256, 2)
k_dist(const float* __restrict__ key, const float* __restrict__ keys, int n) {
    __shared__ unsigned hist[NBINS];
    __shared__ float    ssum[8];
    __shared__ unsigned s_last;
    extern __shared__ float4 tiles[];   // STAGES * TILE_F4

    const int tid  = threadIdx.x;
    const int lane = tid & 31;
    const int wid  = tid >> 5;

    for (int i = tid; i < NBINS; i += 256) hist[i] = 0u;
    __syncthreads();

    const float4* kp = reinterpret_cast<const float4*>(keys);
    const float4  kq = reinterpret_cast<const float4*>(key)[lane];

    const int ntiles = (n + RT - 1) / RT;
    const int G = gridDim.x;
    float lsum = 0.f;

    // issue tile tt into buffer b (always commits, possibly empty group)
    auto issue = [&](int tt, int b) {
        if (tt < ntiles) {
            const int rowbase = tt * RT;
            #pragma unroll
            for (int k = 0; k < 4; k++) {
                int e = tid + k * 256;          // 0..1023
                int r = rowbase + (e >> 5);
                if (r > n - 1) r = n - 1;       // clamp (partial tail tile)
                cp_async16(&tiles[b * TILE_F4 + e], &kp[(size_t)r * 32 + (e & 31)]);
            }
        }
        cp_commit();
    };

    #pragma unroll
    for (int i = 0; i < STAGES; i++) issue(blockIdx.x + i * G, i);

    for (int i = 0; blockIdx.x + i * G < ntiles; i++) {
        const int tt = blockIdx.x + i * G;
        const int b  = i & (STAGES - 1);
        cp_wait3();
        __syncthreads();

        // ---- compute this tile ----
        {
            const int r0 = tt * RT + wid * 4;
            const float4* tb = &tiles[b * TILE_F4 + wid * 4 * 32];
            float4 a0 = tb[lane];
            float4 a1 = tb[32 + lane];
            float4 a2 = tb[64 + lane];
            float4 a3 = tb[96 + lane];

            float dx, dy, dz, dw;
            dx = kq.x - a0.x; dy = kq.y - a0.y; dz = kq.z - a0.z; dw = kq.w - a0.w;
            float s0 = dx*dx + dy*dy + dz*dz + dw*dw;
            dx = kq.x - a1.x; dy = kq.y - a1.y; dz = kq.z - a1.z; dw = kq.w - a1.w;
            float s1 = dx*dx + dy*dy + dz*dz + dw*dw;
            dx = kq.x - a2.x; dy = kq.y - a2.y; dz = kq.z - a2.z; dw = kq.w - a2.w;
            float s2 = dx*dx + dy*dy + dz*dz + dw*dw;
            dx = kq.x - a3.x; dy = kq.y - a3.y; dz = kq.z - a3.z; dw = kq.w - a3.w;
            float s3 = dx*dx + dy*dy + dz*dz + dw*dw;

            #pragma unroll
            for (int o = 16; o >= 4; o >>= 1) {
                s0 += __shfl_xor_sync(0xffffffffu, s0, o);
                s1 += __shfl_xor_sync(0xffffffffu, s1, o);
                s2 += __shfl_xor_sync(0xffffffffu, s2, o);
                s3 += __shfl_xor_sync(0xffffffffu, s3, o);
            }
            const int g = lane >> 3;
            float t = s0;
            if (g == 1) t = s1;
            if (g == 2) t = s2;
            if (g == 3) t = s3;
            t += __shfl_xor_sync(0xffffffffu, t, 2);
            t += __shfl_xor_sync(0xffffffffu, t, 1);
            if ((lane & 7) == 0) {
                const int row = r0 + g;
                if (row < n) {
                    float wv = 1.f / (t + 1e-3f);
                    g_w[row] = wv;
                    atomicAdd(&hist[__float_as_uint(wv) >> 19], 1u);
                    lsum += wv;
                }
            }
        }
        __syncthreads();   // all warps done reading buffer b
        issue(blockIdx.x + (i + STAGES) * G, b);
    }
    cp_wait_all();

    // deterministic block-level weight sum
    #pragma unroll
    for (int o = 16; o; o >>= 1) lsum += __shfl_xor_sync(0xffffffffu, lsum, o);
    if (lane == 0) ssum[wid] = lsum;
    __syncthreads();
    if (tid == 0) {
        float t = 0.f;
        for (int i = 0; i < 8; i++) t += ssum[i];
        g_bsum[blockIdx.x] = t;
    }
    for (int i = tid; i < NBINS; i += 256) {
        unsigned cnt = hist[i];
        if (cnt) atomicAdd(&g_hist[i], cnt);
    }

    // ---- last-block-done: fused threshold computation ----
    __threadfence();
    __syncthreads();
    if (tid == 0)
        s_last = (atomicAdd(&g_done, 1u) == gridDim.x - 1u) ? 1u : 0u;
    __syncthreads();
    if (!s_last) return;

    __shared__ unsigned csum[256];
    __shared__ unsigned suf[256];
    __shared__ float    ss[256];

    for (int i = tid; i < NBINS; i += 256) hist[i] = g_hist[i];

    float t = 0.f;
    for (int i = tid; i < (int)gridDim.x; i += 256) t += g_bsum[i];
    ss[tid] = t;
    __syncthreads();
    for (int o = 128; o; o >>= 1) {
        if (tid < o) ss[tid] += ss[tid + o];
        __syncthreads();
    }
    if (tid == 0) { g_wsum = ss[0]; g_done = 0u; }

    find_boundary(hist, (unsigned)KQW, csum, suf, &g_thresh_bin, &g_above);

    for (int i = tid; i < NBINS; i += 256) g_hist[i] = 0u;   // clean for replay
}

// ------------------------------------------------------------------
// K2: loose compaction — every row with coarse bin >= b* (stores
// weight bits + index). Expected nc ~ O(1000).
// ------------------------------------------------------------------
__global__ void __launch_bounds__(256)
k_compact(int n, int n4) {
    const int gid = blockIdx.x * 256 + threadIdx.x;
    const unsigned tb = g_thresh_bin;
    const float4* w4 = reinterpret_cast<const float4*>(g_w);
    const int stride = gridDim.x * 256;

    for (int i = gid; i < n4; i += stride) {
        float4 v = w4[i];
        unsigned u[4] = { __float_as_uint(v.x), __float_as_uint(v.y),
                          __float_as_uint(v.z), __float_as_uint(v.w) };
        #pragma unroll
        for (int c = 0; c < 4; c++) {
            if (coarse_bin(u[c]) >= tb) {
                unsigned p = atomicAdd(&g_ncand, 1u);
                if (p < CAND_CAP) { g_cand[p] = 4 * i + c; g_cwb[p] = u[c]; }
            }
        }
    }
    if (gid == 0) {
        for (int i = n4 * 4; i < n; i++) {
            unsigned uu = __float_as_uint(g_w[i]);
            if (coarse_bin(uu) >= tb) {
                unsigned p = atomicAdd(&g_ncand, 1u);
                if (p < CAND_CAP) { g_cand[p] = i; g_cwb[p] = uu; }
            }
        }
    }
}

// ------------------------------------------------------------------
// K3 (1 block): in-block radix refine on candidates (sub-bits 7..18),
// filter to ~50-100, exact top-50 rank count (value desc, index asc —
// jax.lax.top_k tiebreak), gather + weighted sum. Resets g_ncand.
// ------------------------------------------------------------------
__global__ void __launch_bounds__(256)
k_final(const float* __restrict__ values, float* __restrict__ out) {
    __shared__ unsigned h[NBINS];
    __shared__ unsigned csum[256];
    __shared__ unsigned suf[256];
    __shared__ unsigned s_sbin, s_m;
    __shared__ float fw[FCAP];
    __shared__ int   fi[FCAP];
    __shared__ float sel_w[KQW];
    __shared__ int   sel_i[KQW];
    __shared__ float part[2 * NCH];

    const int tid = threadIdx.x;
    const unsigned tb = g_thresh_bin;
    int nc = (int)min(g_ncand, (unsigned)CAND_CAP);

    for (int i = tid; i < NBINS; i += 256) h[i] = 0u;
    if (tid == 0) { s_m = 0u; }
    __syncthreads();
    if (tid == 0) g_ncand = 0u;   // clean for next replay

    // histogram of boundary-bin candidates by sub-bits
    for (int i = tid; i < nc; i += 256) {
        unsigned u = g_cwb[i];
        if (coarse_bin(u) == tb) atomicAdd(&h[sub_bin(u)], 1u);
    }
    __syncthreads();

    const unsigned need = (unsigned)KQW - g_above;   // 1..50
    unsigned dummy;
    find_boundary(h, need, csum, suf, &s_sbin, &dummy);
    __syncthreads();
    const unsigned sb = s_sbin;

    // filter candidates
    for (int i = tid; i < nc; i += 256) {
        unsigned u = g_cwb[i];
        if (coarse_bin(u) > tb || sub_bin(u) >= sb) {
            unsigned p = atomicAdd(&s_m, 1u);
            if (p < FCAP) { fw[p] = __uint_as_float(u); fi[p] = g_cand[i]; }
        }
    }
    for (int i = tid; i < KQW; i += 256) { sel_w[i] = 0.f; sel_i[i] = 0; }
    __syncthreads();

    int m = (int)min(s_m, (unsigned)FCAP);

    // exact top-50 by rank counting
    for (int i = tid; i < m; i += 256) {
        const float wi = fw[i];
        const int   ii = fi[i];
        int rank = 0;
        for (int j = 0; j < m; j++) {
            float wj = fw[j];
            rank += (wj > wi) || (wj == wi && fi[j] < ii);
        }
        if (rank < KQW) { sel_w[rank] = wi; sel_i[rank] = ii; }
    }
    __syncthreads();

    const int ns = m < KQW ? m : KQW;
    const int ch = tid & (NCH - 1);
    const int tm = tid >> 7;    // two teams over selections
    float a0 = 0.f, a1 = 0.f, a2 = 0.f, a3 = 0.f;
    int j = tm;
    for (; j + 6 < ns; j += 8) {
        a0 += sel_w[j]     * __ldg(&values[(size_t)sel_i[j]     * NCH + ch]);
        a1 += sel_w[j + 2] * __ldg(&values[(size_t)sel_i[j + 2] * NCH + ch]);
        a2 += sel_w[j + 4] * __ldg(&values[(size_t)sel_i[j + 4] * NCH + ch]);
        a3 += sel_w[j + 6] * __ldg(&values[(size_t)sel_i[j + 6] * NCH + ch]);
    }
    for (; j < ns; j += 2)
        a0 += sel_w[j] * __ldg(&values[(size_t)sel_i[j] * NCH + ch]);
    part[tm * NCH + ch] = ((a0 + a1) + (a2 + a3));
    __syncthreads();
    if (tid < NCH)
        out[tid] = (part[tid] + part[NCH + tid]) / g_wsum;
}

// ------------------------------------------------------------------
extern "C" void kernel_launch(void* const* d_in, const int* in_sizes, int n_in,
                              void* d_out, int out_size) {
    const float* key    = (const float*)d_in[0];
    const float* keys   = (const float*)d_in[1];
    const float* values = (const float*)d_in[2];
    float* out = (float*)d_out;

    const int n = in_sizes[1] / NCH;   // number of memory rows (1,000,000)
    const int dyn = STAGES * TILE_F4 * (int)sizeof(float4);   // 64KB

    static int attr_set = 0;
    if (!attr_set) {
        cudaFuncSetAttribute(k_dist, cudaFuncAttributeMaxDynamicSharedMemorySize, dyn);
        attr_set = 1;
    }

    k_dist   <<<NB_DIST, 256, dyn>>>(key, keys, n);
    k_compact<<<1024, 256>>>(n, n / 4);
    k_final  <<<1, 256>>>(values, out);
}

// round 7
// speedup vs baseline: 1.1874x; 1.1874x over previous
#include <cuda_runtime.h>
#include <cstdint>

#define KQW      50
#define NCH      128          // key/value channels
#define NBINS    4096
#define CAND_CAP 32768
#define FCAP     2048         // filtered candidates in k_final
#define MAXN     1048576
#define NB_DIST  912          // 152 SMs * 6 blocks

// ---- scratch (device globals, zero at module load; kernels self-clean) ----
__device__ float    g_w[MAXN];          // per-row weights (4 MB)
__device__ float    g_bsum[NB_DIST];    // per-block partial sums of weights
__device__ unsigned g_hist[NBINS];      // coarse histogram (bits >> 19)
__device__ float    g_wsum;             // total weight sum
__device__ unsigned g_thresh_bin;       // boundary coarse bin b*
__device__ unsigned g_above;            // count strictly above b* (< 50)
__device__ unsigned g_done;             // k_dist completion counter
__device__ unsigned g_ncand;            // candidate counter
__device__ int      g_cand[CAND_CAP];   // candidate row indices
__device__ unsigned g_cwb[CAND_CAP];    // candidate weight bits

__device__ __forceinline__ unsigned coarse_bin(unsigned u) { return u >> 19; }
__device__ __forceinline__ unsigned sub_bin(unsigned u)    { return (u >> 7) & 0xFFFu; }

// ------------------------------------------------------------------
// Parallel boundary-bin search over a 4096-bin histogram in smem.
// Smallest bin b* with suffix-count >= need. One thread writes out.
// ------------------------------------------------------------------
__device__ __forceinline__ void find_boundary(
    const unsigned* __restrict__ h, unsigned need,
    unsigned* csum, unsigned* suf,
    unsigned* out_bin, unsigned* out_above)
{
    const int tid = threadIdx.x;
    unsigned s = 0u;
    const int base = tid * (NBINS / 256);
    #pragma unroll
    for (int i = 0; i < NBINS / 256; i++) s += h[base + i];
    csum[tid] = s;
    suf[tid]  = s;
    __syncthreads();
    #pragma unroll
    for (int o = 1; o < 256; o <<= 1) {
        unsigned v = suf[tid];
        unsigned add = (tid + o < 256) ? suf[tid + o] : 0u;
        __syncthreads();
        suf[tid] = v + add;
        __syncthreads();
    }
    unsigned above_chunks = (tid + 1 < 256) ? suf[tid + 1] : 0u;
    if (above_chunks < need && suf[tid] >= need) {
        unsigned cum = above_chunks;
        int b = base + (NBINS / 256) - 1;
        for (;; b--) {
            if (b <= base) break;
            if (cum + h[b] >= need) break;
            cum += h[b];
        }
        *out_bin = (unsigned)b;
        *out_above = cum;
    }
}

// ------------------------------------------------------------------
// K1: 512MB streaming pass, occupancy-first (48 warps/SM), 4-row
// unroll, grouped shuffle reduce (3 levels on 4 sums + select + 2).
// Fused threshold via last-block-done.
// ------------------------------------------------------------------
__global__ void __launch_bounds__(256, 6)
k_dist(const float* __restrict__ key, const float* __restrict__ keys, int n) {
    __shared__ unsigned hist[NBINS];
    __shared__ float    ssum[8];
    __shared__ unsigned s_last;
    for (int i = threadIdx.x; i < NBINS; i += 256) hist[i] = 0u;
    __syncthreads();

    const int lane  = threadIdx.x & 31;
    const int wid   = threadIdx.x >> 5;
    const int gwarp = (blockIdx.x * 256 + threadIdx.x) >> 5;
    const int nwarp = (gridDim.x * 256) >> 5;

    const float4* kp = reinterpret_cast<const float4*>(keys);
    const float4  kq = reinterpret_cast<const float4*>(key)[lane];

    float lsum = 0.f;
    int row = gwarp;

    for (; row + 3 * nwarp < n; row += 4 * nwarp) {
        float4 a0 = __ldcs(&kp[(size_t)row * 32 + lane]);
        float4 a1 = __ldcs(&kp[(size_t)(row +     nwarp) * 32 + lane]);
        float4 a2 = __ldcs(&kp[(size_t)(row + 2 * nwarp) * 32 + lane]);
        float4 a3 = __ldcs(&kp[(size_t)(row + 3 * nwarp) * 32 + lane]);

        float dx, dy, dz, dw;
        dx = kq.x - a0.x; dy = kq.y - a0.y; dz = kq.z - a0.z; dw = kq.w - a0.w;
        float s0 = dx*dx + dy*dy + dz*dz + dw*dw;
        dx = kq.x - a1.x; dy = kq.y - a1.y; dz = kq.z - a1.z; dw = kq.w - a1.w;
        float s1 = dx*dx + dy*dy + dz*dz + dw*dw;
        dx = kq.x - a2.x; dy = kq.y - a2.y; dz = kq.z - a2.z; dw = kq.w - a2.w;
        float s2 = dx*dx + dy*dy + dz*dz + dw*dw;
        dx = kq.x - a3.x; dy = kq.y - a3.y; dz = kq.z - a3.z; dw = kq.w - a3.w;
        float s3 = dx*dx + dy*dy + dz*dz + dw*dw;

        #pragma unroll
        for (int o = 16; o >= 4; o >>= 1) {
            s0 += __shfl_xor_sync(0xffffffffu, s0, o);
            s1 += __shfl_xor_sync(0xffffffffu, s1, o);
            s2 += __shfl_xor_sync(0xffffffffu, s2, o);
            s3 += __shfl_xor_sync(0xffffffffu, s3, o);
        }
        const int g = lane >> 3;
        float t = s0;
        if (g == 1) t = s1;
        if (g == 2) t = s2;
        if (g == 3) t = s3;
        t += __shfl_xor_sync(0xffffffffu, t, 2);
        t += __shfl_xor_sync(0xffffffffu, t, 1);
        if ((lane & 7) == 0) {
            float wv = 1.f / (t + 1e-3f);
            g_w[row + g * nwarp] = wv;
            atomicAdd(&hist[__float_as_uint(wv) >> 19], 1u);
            lsum += wv;
        }
    }
    for (; row < n; row += nwarp) {
        float4 a = __ldcs(&kp[(size_t)row * 32 + lane]);
        float dx = kq.x - a.x, dy = kq.y - a.y, dz = kq.z - a.z, dw = kq.w - a.w;
        float s0 = dx*dx + dy*dy + dz*dz + dw*dw;
        #pragma unroll
        for (int o = 16; o; o >>= 1) s0 += __shfl_xor_sync(0xffffffffu, s0, o);
        if (lane == 0) {
            float wv = 1.f / (s0 + 1e-3f);
            g_w[row] = wv;
            lsum += wv;
            atomicAdd(&hist[__float_as_uint(wv) >> 19], 1u);
        }
    }

    // deterministic block-level weight sum
    #pragma unroll
    for (int o = 16; o; o >>= 1) lsum += __shfl_xor_sync(0xffffffffu, lsum, o);
    if (lane == 0) ssum[wid] = lsum;
    __syncthreads();
    if (threadIdx.x == 0) {
        float t = 0.f;
        for (int i = 0; i < 8; i++) t += ssum[i];
        g_bsum[blockIdx.x] = t;
    }
    for (int i = threadIdx.x; i < NBINS; i += 256) {
        unsigned cnt = hist[i];
        if (cnt) atomicAdd(&g_hist[i], cnt);
    }

    // ---- last-block-done: fused threshold computation ----
    __threadfence();
    __syncthreads();
    if (threadIdx.x == 0)
        s_last = (atomicAdd(&g_done, 1u) == gridDim.x - 1u) ? 1u : 0u;
    __syncthreads();
    if (!s_last) return;

    __shared__ unsigned csum[256];
    __shared__ unsigned suf[256];
    __shared__ float    ss[256];
    const int tid = threadIdx.x;

    for (int i = tid; i < NBINS; i += 256) hist[i] = g_hist[i];

    float t = 0.f;
    for (int i = tid; i < (int)gridDim.x; i += 256) t += g_bsum[i];
    ss[tid] = t;
    __syncthreads();
    for (int o = 128; o; o >>= 1) {
        if (tid < o) ss[tid] += ss[tid + o];
        __syncthreads();
    }
    if (tid == 0) { g_wsum = ss[0]; g_done = 0u; }

    find_boundary(hist, (unsigned)KQW, csum, suf, &g_thresh_bin, &g_above);

    for (int i = tid; i < NBINS; i += 256) g_hist[i] = 0u;   // clean for replay
}

// ------------------------------------------------------------------
// K2: loose compaction — every row with coarse bin >= b* (stores
// weight bits + index). Expected nc ~ O(1000).
// ------------------------------------------------------------------
__global__ void __launch_bounds__(256)
k_compact(int n, int n4) {
    const int gid = blockIdx.x * 256 + threadIdx.x;
    const unsigned tb = g_thresh_bin;
    const float4* w4 = reinterpret_cast<const float4*>(g_w);
    const int stride = gridDim.x * 256;

    for (int i = gid; i < n4; i += stride) {
        float4 v = w4[i];
        unsigned u[4] = { __float_as_uint(v.x), __float_as_uint(v.y),
                          __float_as_uint(v.z), __float_as_uint(v.w) };
        #pragma unroll
        for (int c = 0; c < 4; c++) {
            if (coarse_bin(u[c]) >= tb) {
                unsigned p = atomicAdd(&g_ncand, 1u);
                if (p < CAND_CAP) { g_cand[p] = 4 * i + c; g_cwb[p] = u[c]; }
            }
        }
    }
    if (gid == 0) {
        for (int i = n4 * 4; i < n; i++) {
            unsigned uu = __float_as_uint(g_w[i]);
            if (coarse_bin(uu) >= tb) {
                unsigned p = atomicAdd(&g_ncand, 1u);
                if (p < CAND_CAP) { g_cand[p] = i; g_cwb[p] = uu; }
            }
        }
    }
}

// ------------------------------------------------------------------
// K3 (1 block): in-block radix refine on candidates (sub-bits 7..18),
// filter to ~50-100, exact top-50 rank count (value desc, index asc —
// jax.lax.top_k tiebreak), gather + weighted sum. Resets g_ncand.
// ------------------------------------------------------------------
__global__ void __launch_bounds__(256)
k_final(const float* __restrict__ values, float* __restrict__ out) {
    __shared__ unsigned h[NBINS];
    __shared__ unsigned csum[256];
    __shared__ unsigned suf[256];
    __shared__ unsigned s_sbin, s_m;
    __shared__ float fw[FCAP];
    __shared__ int   fi[FCAP];
    __shared__ float sel_w[KQW];
    __shared__ int   sel_i[KQW];
    __shared__ float part[2 * NCH];

    const int tid = threadIdx.x;
    const unsigned tb = g_thresh_bin;
    int nc = (int)min(g_ncand, (unsigned)CAND_CAP);

    for (int i = tid; i < NBINS; i += 256) h[i] = 0u;
    if (tid == 0) { s_m = 0u; }
    __syncthreads();
    if (tid == 0) g_ncand = 0u;   // clean for next replay

    // histogram of boundary-bin candidates by sub-bits
    for (int i = tid; i < nc; i += 256) {
        unsigned u = g_cwb[i];
        if (coarse_bin(u) == tb) atomicAdd(&h[sub_bin(u)], 1u);
    }
    __syncthreads();

    const unsigned need = (unsigned)KQW - g_above;   // 1..50
    unsigned dummy;
    find_boundary(h, need, csum, suf, &s_sbin, &dummy);
    __syncthreads();
    const unsigned sb = s_sbin;

    // filter candidates
    for (int i = tid; i < nc; i += 256) {
        unsigned u = g_cwb[i];
        if (coarse_bin(u) > tb || sub_bin(u) >= sb) {
            unsigned p = atomicAdd(&s_m, 1u);
            if (p < FCAP) { fw[p] = __uint_as_float(u); fi[p] = g_cand[i]; }
        }
    }
    for (int i = tid; i < KQW; i += 256) { sel_w[i] = 0.f; sel_i[i] = 0; }
    __syncthreads();

    int m = (int)min(s_m, (unsigned)FCAP);

    // exact top-50 by rank counting
    for (int i = tid; i < m; i += 256) {
        const float wi = fw[i];
        const int   ii = fi[i];
        int rank = 0;
        for (int j = 0; j < m; j++) {
            float wj = fw[j];
            rank += (wj > wi) || (wj == wi && fi[j] < ii);
        }
        if (rank < KQW) { sel_w[rank] = wi; sel_i[rank] = ii; }
    }
    __syncthreads();

    const int ns = m < KQW ? m : KQW;
    const int ch = tid & (NCH - 1);
    const int tm = tid >> 7;    // two teams over selections
    float a0 = 0.f, a1 = 0.f, a2 = 0.f, a3 = 0.f;
    int j = tm;
    for (; j + 6 < ns; j += 8) {
        a0 += sel_w[j]     * __ldg(&values[(size_t)sel_i[j]     * NCH + ch]);
        a1 += sel_w[j + 2] * __ldg(&values[(size_t)sel_i[j + 2] * NCH + ch]);
        a2 += sel_w[j + 4] * __ldg(&values[(size_t)sel_i[j + 4] * NCH + ch]);
        a3 += sel_w[j + 6] * __ldg(&values[(size_t)sel_i[j + 6] * NCH + ch]);
    }
    for (; j < ns; j += 2)
        a0 += sel_w[j] * __ldg(&values[(size_t)sel_i[j] * NCH + ch]);
    part[tm * NCH + ch] = ((a0 + a1) + (a2 + a3));
    __syncthreads();
    if (tid < NCH)
        out[tid] = (part[tid] + part[NCH + tid]) / g_wsum;
}

// ------------------------------------------------------------------
extern "C" void kernel_launch(void* const* d_in, const int* in_sizes, int n_in,
                              void* d_out, int out_size) {
    const float* key    = (const float*)d_in[0];
    const float* keys   = (const float*)d_in[1];
    const float* values = (const float*)d_in[2];
    float* out = (float*)d_out;

    const int n = in_sizes[1] / NCH;   // number of memory rows (1,000,000)

    k_dist   <<<NB_DIST, 256>>>(key, keys, n);
    k_compact<<<1024, 256>>>(n, n / 4);
    k_final  <<<1, 256>>>(values, out);
}